// round 16
// baseline (speedup 1.0000x reference)
#include <cuda_runtime.h>
#include <cuda_bf16.h>
#include <cuda_fp16.h>
#include <mma.h>

using namespace nvcuda;

#define MAXN 100000
#define IN_C 128
#define OUT_C 64
#define CAP 64             // bucket capacity per node (deg ~Poisson(16), max ~45)

#define A_LD 136           // halves per A row (128 + 8 pad; 272B = 17*16B ok for wmma)
#define B_LD 72            // halves per B row (64 + 8 pad; 144B = 9*16B ok)
#define GEMM_SMEM (128 * A_LD * 2 + 128 * B_LD * 2)   // 34816 + 18432 = 53248 B

// ---------------------------------------------------------------------------
// Scratch (__device__ globals per allocation-free rule)
__device__ __half g_xwh[(size_t)MAXN * OUT_C];       // UNSCALED xw fp16 [N,64]
__device__ int    g_cnt[MAXN];                        // per-node in-degree
__device__ int    g_bucket[(size_t)MAXN * CAP];       // src ids per dst (25.6 MB)

// ---------------------------------------------------------------------------
// Single edge pass: bucket-scatter src by dst. 4 edges per thread (int4 loads).
__global__ void fill_bucket_kernel(const int* __restrict__ src,
                                   const int* __restrict__ dst, int e) {
    int i = blockIdx.x * blockDim.x + threadIdx.x;
    int base = i * 4;
    if (base + 3 < e) {
        int4 d = *(const int4*)(dst + base);
        int4 s = *(const int4*)(src + base);
        int p;
        p = atomicAdd(&g_cnt[d.x], 1); if (p < CAP) g_bucket[(size_t)d.x * CAP + p] = s.x;
        p = atomicAdd(&g_cnt[d.y], 1); if (p < CAP) g_bucket[(size_t)d.y * CAP + p] = s.y;
        p = atomicAdd(&g_cnt[d.z], 1); if (p < CAP) g_bucket[(size_t)d.z * CAP + p] = s.z;
        p = atomicAdd(&g_cnt[d.w], 1); if (p < CAP) g_bucket[(size_t)d.w * CAP + p] = s.w;
    } else {
        for (int j = base; j < e; j++) {
            int d = dst[j];
            int p = atomicAdd(&g_cnt[d], 1);
            if (p < CAP) g_bucket[(size_t)d * CAP + p] = src[j];
        }
    }
}

// ---------------------------------------------------------------------------
// Tensor-core GEMM v2: full tile staged in ONE pass (max MLP), then 8 MMA
// k-steps uninterrupted. Dynamic smem (53.2 KB).
__global__ __launch_bounds__(256) void gemm_kernel(
    const float* __restrict__ x,
    const float* __restrict__ w,      // [128,64] row-major
    int n)
{
    extern __shared__ __align__(16) unsigned char smem_raw[];
    __half* As = (__half*)smem_raw;                       // [128][A_LD]
    __half* Bs = (__half*)(smem_raw + 128 * A_LD * 2);    // [128][B_LD]
    float*  Cs = (float*)smem_raw;                        // [64][68] (epilogue)

    const int tid  = threadIdx.x;
    const int warp = tid >> 5;
    const int r0   = blockIdx.x * 128;

    const float4* x4 = (const float4*)x;   // row stride 32 float4
    const float4* w4 = (const float4*)w;   // row stride 16 float4

    // Stage FULL A tile: 128 rows x 32 float4 = 4096 -> 16 per thread.
    #pragma unroll
    for (int i = tid; i < 128 * 32; i += 256) {
        int row = i >> 5, c4 = i & 31;
        int rg = r0 + row;
        float4 v = (rg < n) ? x4[(size_t)rg * 32 + c4]
                            : make_float4(0.f, 0.f, 0.f, 0.f);
        __half2* dstp = (__half2*)(As + row * A_LD + c4 * 4);
        dstp[0] = __floats2half2_rn(v.x, v.y);
        dstp[1] = __floats2half2_rn(v.z, v.w);
    }
    // Stage FULL B: 128 K-rows x 16 float4 = 2048 -> 8 per thread.
    #pragma unroll
    for (int i = tid; i < 128 * 16; i += 256) {
        int row = i >> 4, c4 = i & 15;
        float4 v = w4[(size_t)row * 16 + c4];
        __half2* dstp = (__half2*)(Bs + row * B_LD + c4 * 4);
        dstp[0] = __floats2half2_rn(v.x, v.y);
        dstp[1] = __floats2half2_rn(v.z, v.w);
    }
    __syncthreads();

    wmma::fragment<wmma::accumulator, 16, 16, 16, float> acc[4];
    #pragma unroll
    for (int t = 0; t < 4; t++) wmma::fill_fragment(acc[t], 0.0f);

    #pragma unroll
    for (int k = 0; k < 8; k++) {
        wmma::fragment<wmma::matrix_a, 16, 16, 16, __half, wmma::row_major> a;
        wmma::load_matrix_sync(a, As + (warp * 16) * A_LD + k * 16, A_LD);
        #pragma unroll
        for (int t = 0; t < 4; t++) {
            wmma::fragment<wmma::matrix_b, 16, 16, 16, __half, wmma::row_major> b;
            wmma::load_matrix_sync(b, Bs + (k * 16) * B_LD + t * 16, B_LD);
            wmma::mma_sync(acc[t], a, b, acc[t]);
        }
    }

    // Epilogue in two halves (64 rows each) via smem staging (reuses As space).
    __half2* xwh2 = (__half2*)g_xwh;
    #pragma unroll
    for (int h = 0; h < 2; h++) {
        __syncthreads();
        if ((warp >> 2) == h) {
            int wl = warp & 3;
            #pragma unroll
            for (int t = 0; t < 4; t++)
                wmma::store_matrix_sync(Cs + (wl * 16) * 68 + t * 16, acc[t],
                                        68, wmma::mem_row_major);
        }
        __syncthreads();
        #pragma unroll
        for (int i = tid; i < 64 * 32; i += 256) {
            int row = i >> 5, hc = i & 31;
            int rg = r0 + h * 64 + row;
            if (rg < n) {
                float f0 = Cs[row * 68 + hc * 2];
                float f1 = Cs[row * 68 + hc * 2 + 1];
                xwh2[(size_t)rg * 32 + hc] = __floats2half2_rn(f0, f1);
            }
        }
    }
}

// ---------------------------------------------------------------------------
// Gather-reduce: 16 lanes per node (2 nodes/warp), 2 edges/node/iter,
// software-pipelined bucket index prefetch, inline rsqrt dinv.
__global__ __launch_bounds__(256) void gather_kernel(
    const float* __restrict__ bias,
    float* __restrict__ out, int n)
{
    int wid = (blockIdx.x * blockDim.x + threadIdx.x) >> 4;
    int hl  = threadIdx.x & 15;
    if (wid >= n) return;

    const int g  = hl >> 3;
    const int l8 = hl & 7;
    const unsigned team = 0xffffu << (threadIdx.x & 16);

    int degf = g_cnt[wid];
    int deg  = degf > CAP ? CAP : degf;
    float di = rsqrtf((float)(degf + 1));

    const float4* xwrows = (const float4*)g_xwh + l8;
    const int*    bkt    = g_bucket + (size_t)wid * CAP;

    float2 a0 = make_float2(0.f, 0.f);
    float2 a1 = make_float2(0.f, 0.f);
    float2 a2 = make_float2(0.f, 0.f);
    float2 a3 = make_float2(0.f, 0.f);

    if (g == 0) {   // self-loop term
        float4 hv = __ldg(&xwrows[wid * 8]);
        const __half2* h = (const __half2*)&hv;
        float2 v;
        v = __half22float2(h[0]); a0.x = v.x * di; a0.y = v.y * di;
        v = __half22float2(h[1]); a1.x = v.x * di; a1.y = v.y * di;
        v = __half22float2(h[2]); a2.x = v.x * di; a2.y = v.y * di;
        v = __half22float2(h[3]); a3.x = v.x * di; a3.y = v.y * di;
    }

    int k = g;
    int s_next = (k < deg) ? __ldg(&bkt[k]) : 0;
    #pragma unroll 2
    for (; k < deg; k += 2) {
        int s = s_next;
        if (k + 2 < deg) s_next = __ldg(&bkt[k + 2]);
        float ds = rsqrtf((float)(__ldg(&g_cnt[s]) + 1));
        float4 hv = __ldg(&xwrows[s * 8]);
        const __half2* h = (const __half2*)&hv;
        float2 v;
        v = __half22float2(h[0]); a0.x += v.x * ds; a0.y += v.y * ds;
        v = __half22float2(h[1]); a1.x += v.x * ds; a1.y += v.y * ds;
        v = __half22float2(h[2]); a2.x += v.x * ds; a2.y += v.y * ds;
        v = __half22float2(h[3]); a3.x += v.x * ds; a3.y += v.y * ds;
    }

    a0.x += __shfl_xor_sync(team, a0.x, 8);
    a0.y += __shfl_xor_sync(team, a0.y, 8);
    a1.x += __shfl_xor_sync(team, a1.x, 8);
    a1.y += __shfl_xor_sync(team, a1.y, 8);
    a2.x += __shfl_xor_sync(team, a2.x, 8);
    a2.y += __shfl_xor_sync(team, a2.y, 8);
    a3.x += __shfl_xor_sync(team, a3.x, 8);
    a3.y += __shfl_xor_sync(team, a3.y, 8);

    if (g == 0) {
        const float4* b4 = (const float4*)bias;
        float4 b0 = __ldg(&b4[l8 * 2 + 0]);
        float4 b1 = __ldg(&b4[l8 * 2 + 1]);
        float4 o0, o1;
        o0.x = a0.x * di + b0.x;  o0.y = a0.y * di + b0.y;
        o0.z = a1.x * di + b0.z;  o0.w = a1.y * di + b0.w;
        o1.x = a2.x * di + b1.x;  o1.y = a2.y * di + b1.y;
        o1.z = a3.x * di + b1.z;  o1.w = a3.y * di + b1.w;
        float4* orow = (float4*)(out + (size_t)wid * 64);
        orow[l8 * 2 + 0] = o0;
        orow[l8 * 2 + 1] = o1;
    }
}

// ---------------------------------------------------------------------------
extern "C" void kernel_launch(void* const* d_in, const int* in_sizes, int n_in,
                              void* d_out, int out_size) {
    const float* x    = (const float*)d_in[0];
    const int*   ei   = (const int*)d_in[1];     // [2, E] int32
    const float* w    = (const float*)d_in[2];   // [128, 64]
    const float* bias = (const float*)d_in[3];   // [64]
    float*       out  = (float*)d_out;

    const int n = in_sizes[0] / IN_C;
    const int e = in_sizes[1] / 2;

    const int* src = ei;        // edge_index[0]
    const int* dst = ei + e;    // edge_index[1]

    // one-time host-side setup (no device allocations)
    static cudaStream_t s_side = nullptr;
    static cudaEvent_t  ev_fork = nullptr, ev_gemm = nullptr;
    static int*         cnt_addr = nullptr;
    if (s_side == nullptr) {
        cudaStreamCreateWithFlags(&s_side, cudaStreamNonBlocking);
        cudaEventCreateWithFlags(&ev_fork, cudaEventDisableTiming);
        cudaEventCreateWithFlags(&ev_gemm, cudaEventDisableTiming);
        cudaGetSymbolAddress((void**)&cnt_addr, g_cnt);
        cudaFuncSetAttribute(gemm_kernel,
                             cudaFuncAttributeMaxDynamicSharedMemorySize,
                             GEMM_SMEM);
    }

    // fork: tensor-core gemm (independent branch) on side stream
    cudaEventRecord(ev_fork, 0);
    cudaStreamWaitEvent(s_side, ev_fork, 0);
    gemm_kernel<<<(n + 127) / 128, 256, GEMM_SMEM, s_side>>>(x, w, n);
    cudaEventRecord(ev_gemm, s_side);

    // main branch: zero counters (memset node) + bucket build (single pass)
    cudaMemsetAsync(cnt_addr, 0, (size_t)n * sizeof(int), 0);
    int eq = (e + 3) / 4;
    fill_bucket_kernel<<<(eq + 255) / 256, 256>>>(src, dst, e);

    // join, then gather (16 lanes per node)
    cudaStreamWaitEvent(0, ev_gemm, 0);
    int blocks = (n * 16 + 255) / 256;
    gather_kernel<<<blocks, 256>>>(bias, out, n);
}

// round 17
// speedup vs baseline: 1.1300x; 1.1300x over previous
#include <cuda_runtime.h>
#include <cuda_bf16.h>
#include <cuda_fp16.h>
#include <mma.h>

using namespace nvcuda;

#define MAXN 100000
#define IN_C 128
#define OUT_C 64
#define CAP 64             // bucket capacity per node (deg ~Poisson(16), max ~45)

// ---------------------------------------------------------------------------
// Scratch (__device__ globals per allocation-free rule)
__device__ __half g_xwh[(size_t)MAXN * OUT_C];       // UNSCALED xw fp16 [N,64]
__device__ int    g_cnt[MAXN];                        // per-node in-degree
__device__ int    g_bucket[(size_t)MAXN * CAP];       // src ids per dst (25.6 MB)

__device__ __forceinline__ float4 ldcs4(const float4* p) {
    float4 v;
    asm volatile("ld.global.cs.v4.f32 {%0,%1,%2,%3}, [%4];"
                 : "=f"(v.x), "=f"(v.y), "=f"(v.z), "=f"(v.w) : "l"(p));
    return v;
}
__device__ __forceinline__ int4 ldcs_i4(const int4* p) {
    int4 v;
    asm volatile("ld.global.cs.v4.s32 {%0,%1,%2,%3}, [%4];"
                 : "=r"(v.x), "=r"(v.y), "=r"(v.z), "=r"(v.w) : "l"(p));
    return v;
}

// ---------------------------------------------------------------------------
// Single edge pass: bucket-scatter src by dst. 4 edges per thread (int4,
// streaming loads — edge list is read-once).
__global__ void fill_bucket_kernel(const int* __restrict__ src,
                                   const int* __restrict__ dst, int e) {
    int i = blockIdx.x * blockDim.x + threadIdx.x;
    int base = i * 4;
    if (base + 3 < e) {
        int4 d = ldcs_i4((const int4*)(dst + base));
        int4 s = ldcs_i4((const int4*)(src + base));
        int p;
        p = atomicAdd(&g_cnt[d.x], 1); if (p < CAP) g_bucket[(size_t)d.x * CAP + p] = s.x;
        p = atomicAdd(&g_cnt[d.y], 1); if (p < CAP) g_bucket[(size_t)d.y * CAP + p] = s.y;
        p = atomicAdd(&g_cnt[d.z], 1); if (p < CAP) g_bucket[(size_t)d.z * CAP + p] = s.z;
        p = atomicAdd(&g_cnt[d.w], 1); if (p < CAP) g_bucket[(size_t)d.w * CAP + p] = s.w;
    } else {
        for (int j = base; j < e; j++) {
            int d = dst[j];
            int p = atomicAdd(&g_cnt[d], 1);
            if (p < CAP) g_bucket[(size_t)d * CAP + p] = src[j];
        }
    }
}

// ---------------------------------------------------------------------------
// Tensor-core GEMM (R15 structure): g_xwh[r] = half(x[r] @ W), wmma fp32 acc.
// K in 2 chunks of 64. Streaming loads for x (read-once).
__global__ __launch_bounds__(256) void gemm_kernel(
    const float* __restrict__ x,
    const float* __restrict__ w,      // [128,64] row-major
    int n)
{
    static __shared__ __align__(16) unsigned char smem_raw[27648];
    __half* As = (__half*)smem_raw;                 // [128][72] halves
    __half* Bs = (__half*)(smem_raw + 18432);       // [64][72]  halves
    float*  Cs = (float*)smem_raw;                  // [64][68]  floats (epilogue)

    const int tid  = threadIdx.x;
    const int warp = tid >> 5;
    const int r0   = blockIdx.x * 128;

    wmma::fragment<wmma::accumulator, 16, 16, 16, float> acc[4];
    #pragma unroll
    for (int t = 0; t < 4; t++) wmma::fill_fragment(acc[t], 0.0f);

    const float4* x4 = (const float4*)x;   // row stride 32 float4
    const float4* w4 = (const float4*)w;   // row stride 16 float4

    for (int ch = 0; ch < 2; ch++) {
        __syncthreads();
        #pragma unroll
        for (int i = tid; i < 128 * 16; i += 256) {
            int row = i >> 4, c4 = i & 15;
            int rg = r0 + row;
            float4 v = (rg < n) ? ldcs4(&x4[(size_t)rg * 32 + ch * 16 + c4])
                                : make_float4(0.f, 0.f, 0.f, 0.f);
            __half2* dstp = (__half2*)(As + row * 72 + c4 * 4);
            dstp[0] = __floats2half2_rn(v.x, v.y);
            dstp[1] = __floats2half2_rn(v.z, v.w);
        }
        #pragma unroll
        for (int i = tid; i < 64 * 16; i += 256) {
            int row = i >> 4, c4 = i & 15;
            float4 v = w4[(size_t)(ch * 64 + row) * 16 + c4];
            __half2* dstp = (__half2*)(Bs + row * 72 + c4 * 4);
            dstp[0] = __floats2half2_rn(v.x, v.y);
            dstp[1] = __floats2half2_rn(v.z, v.w);
        }
        __syncthreads();

        #pragma unroll
        for (int k = 0; k < 4; k++) {
            wmma::fragment<wmma::matrix_a, 16, 16, 16, __half, wmma::row_major> a;
            wmma::load_matrix_sync(a, As + (warp * 16) * 72 + k * 16, 72);
            #pragma unroll
            for (int t = 0; t < 4; t++) {
                wmma::fragment<wmma::matrix_b, 16, 16, 16, __half, wmma::row_major> b;
                wmma::load_matrix_sync(b, Bs + (k * 16) * 72 + t * 16, 72);
                wmma::mma_sync(acc[t], a, b, acc[t]);
            }
        }
    }

    __half2* xwh2 = (__half2*)g_xwh;
    #pragma unroll
    for (int h = 0; h < 2; h++) {
        __syncthreads();
        if ((warp >> 2) == h) {
            int wl = warp & 3;
            #pragma unroll
            for (int t = 0; t < 4; t++)
                wmma::store_matrix_sync(Cs + (wl * 16) * 68 + t * 16, acc[t],
                                        68, wmma::mem_row_major);
        }
        __syncthreads();
        #pragma unroll
        for (int i = tid; i < 64 * 32; i += 256) {
            int row = i >> 5, hc = i & 31;
            int rg = r0 + h * 64 + row;
            if (rg < n) {
                float f0 = Cs[row * 68 + hc * 2];
                float f1 = Cs[row * 68 + hc * 2 + 1];
                xwh2[(size_t)rg * 32 + hc] = __floats2half2_rn(f0, f1);
            }
        }
    }
}

// ---------------------------------------------------------------------------
// Gather-reduce (R15 measured-best): 16 lanes per node (2 nodes/warp),
// 2 edges/node/iter, pipelined bucket prefetch, inline rsqrt dinv.
__global__ __launch_bounds__(256) void gather_kernel(
    const float* __restrict__ bias,
    float* __restrict__ out, int n)
{
    int wid = (blockIdx.x * blockDim.x + threadIdx.x) >> 4;
    int hl  = threadIdx.x & 15;
    if (wid >= n) return;

    const int g  = hl >> 3;
    const int l8 = hl & 7;
    const unsigned team = 0xffffu << (threadIdx.x & 16);

    int degf = g_cnt[wid];
    int deg  = degf > CAP ? CAP : degf;
    float di = rsqrtf((float)(degf + 1));

    const float4* xwrows = (const float4*)g_xwh + l8;
    const int*    bkt    = g_bucket + (size_t)wid * CAP;

    float2 a0 = make_float2(0.f, 0.f);
    float2 a1 = make_float2(0.f, 0.f);
    float2 a2 = make_float2(0.f, 0.f);
    float2 a3 = make_float2(0.f, 0.f);

    if (g == 0) {   // self-loop term
        float4 hv = __ldg(&xwrows[wid * 8]);
        const __half2* h = (const __half2*)&hv;
        float2 v;
        v = __half22float2(h[0]); a0.x = v.x * di; a0.y = v.y * di;
        v = __half22float2(h[1]); a1.x = v.x * di; a1.y = v.y * di;
        v = __half22float2(h[2]); a2.x = v.x * di; a2.y = v.y * di;
        v = __half22float2(h[3]); a3.x = v.x * di; a3.y = v.y * di;
    }

    int k = g;
    int s_next = (k < deg) ? __ldg(&bkt[k]) : 0;
    #pragma unroll 2
    for (; k < deg; k += 2) {
        int s = s_next;
        if (k + 2 < deg) s_next = __ldg(&bkt[k + 2]);
        float ds = rsqrtf((float)(__ldg(&g_cnt[s]) + 1));
        float4 hv = __ldg(&xwrows[s * 8]);
        const __half2* h = (const __half2*)&hv;
        float2 v;
        v = __half22float2(h[0]); a0.x += v.x * ds; a0.y += v.y * ds;
        v = __half22float2(h[1]); a1.x += v.x * ds; a1.y += v.y * ds;
        v = __half22float2(h[2]); a2.x += v.x * ds; a2.y += v.y * ds;
        v = __half22float2(h[3]); a3.x += v.x * ds; a3.y += v.y * ds;
    }

    a0.x += __shfl_xor_sync(team, a0.x, 8);
    a0.y += __shfl_xor_sync(team, a0.y, 8);
    a1.x += __shfl_xor_sync(team, a1.x, 8);
    a1.y += __shfl_xor_sync(team, a1.y, 8);
    a2.x += __shfl_xor_sync(team, a2.x, 8);
    a2.y += __shfl_xor_sync(team, a2.y, 8);
    a3.x += __shfl_xor_sync(team, a3.x, 8);
    a3.y += __shfl_xor_sync(team, a3.y, 8);

    if (g == 0) {
        const float4* b4 = (const float4*)bias;
        float4 b0 = __ldg(&b4[l8 * 2 + 0]);
        float4 b1 = __ldg(&b4[l8 * 2 + 1]);
        float4 o0, o1;
        o0.x = a0.x * di + b0.x;  o0.y = a0.y * di + b0.y;
        o0.z = a1.x * di + b0.z;  o0.w = a1.y * di + b0.w;
        o1.x = a2.x * di + b1.x;  o1.y = a2.y * di + b1.y;
        o1.z = a3.x * di + b1.z;  o1.w = a3.y * di + b1.w;
        float4* orow = (float4*)(out + (size_t)wid * 64);
        orow[l8 * 2 + 0] = o0;
        orow[l8 * 2 + 1] = o1;
    }
}

// ---------------------------------------------------------------------------
extern "C" void kernel_launch(void* const* d_in, const int* in_sizes, int n_in,
                              void* d_out, int out_size) {
    const float* x    = (const float*)d_in[0];
    const int*   ei   = (const int*)d_in[1];     // [2, E] int32
    const float* w    = (const float*)d_in[2];   // [128, 64]
    const float* bias = (const float*)d_in[3];   // [64]
    float*       out  = (float*)d_out;

    const int n = in_sizes[0] / IN_C;
    const int e = in_sizes[1] / 2;

    const int* src = ei;        // edge_index[0]
    const int* dst = ei + e;    // edge_index[1]

    static int* cnt_addr = nullptr;
    if (cnt_addr == nullptr) {
        cudaGetSymbolAddress((void**)&cnt_addr, g_cnt);
    }

    // Single stream, no fork: eliminate cross-kernel DRAM/L2 contention and
    // 4 event/wait graph nodes. Order: gemm, memset, fill, gather.
    gemm_kernel<<<(n + 127) / 128, 256>>>(x, w, n);
    cudaMemsetAsync(cnt_addr, 0, (size_t)n * sizeof(int), 0);
    int eq = (e + 3) / 4;
    fill_bucket_kernel<<<(eq + 255) / 256, 256>>>(src, dst, e);
    int blocks = (n * 16 + 255) / 256;
    gather_kernel<<<blocks, 256>>>(bias, out, n);
}